// round 15
// baseline (speedup 1.0000x reference)
#include <cuda_runtime.h>

#define N_NODES 8192
#define NV4 (N_NODES / 4)       // 2048 float4 per row
#define PSI 64

#define PF_BLOCKS 256           // K1 prefetch blocks
#define PF_ROWS 512             // 16 MB warmed into L2 (≈ scatter+node duration)
#define SC_BLOCKS 1024          // K1 scatter blocks (nnz / 256)
#define NODE_BLOCKS 16          // K1 node-MLP blocks (spin on sc_done)

#define ROW_BLOCKS 1184         // K2: 148 SMs x 8 blocks, grid-stride rows
#define GA_BLOCKS 128           // K2 gather blocks (spin on row_done)

// __device__ scratch (no allocations allowed).  All zero-init at load; the
// pipeline restores every word to its pre-launch value each replay
// (read-then-zero for g_agg, counter reset by the last gather block).
__device__ float g_agg[N_NODES];
__device__ float g_t[N_NODES];
__device__ float g_s[N_NODES];
__device__ float g_sink;                 // prefetch DCE guard (never written)
__device__ unsigned int g_sc_done = 0;   // scatter blocks finished
__device__ unsigned int g_row_done = 0;  // row blocks finished
__device__ unsigned int g_ga_done = 0;   // gather blocks finished

// ---------------------------------------------------------------------------
// K1: heterogeneous blocks.
//  [0, PF_BLOCKS)                 : L2 prefetch of adj rows 0..PF_ROWS-1
//  [PF_BLOCKS, PF_BLOCKS+SC_BLOCKS): edge MLP + scatter-add into g_agg
//  [.., +NODE_BLOCKS)             : spin on sc_done, then node MLP -> g_t,
//                                   re-zero g_agg (replay reset)
// Node blocks have the highest bids -> dispatched after all scatter blocks,
// so the internal spin cannot deadlock.
// Edge-MLP algebraic fast path (zero hidden bias, verified on device):
//   f(v) = v*Cp + b2 (v>=0), v*Cn + b2 (v<0); generic fallback otherwise.
// ---------------------------------------------------------------------------
__global__ __launch_bounds__(256) void k_front(
        const float* __restrict__ adj,
        const int* __restrict__ col,
        const float* __restrict__ values,
        const float* __restrict__ w1e, const float* __restrict__ b1e,
        const float* __restrict__ w2e, const float* __restrict__ b2e,
        const float* __restrict__ w1n, const float* __restrict__ b1n,
        const float* __restrict__ w2n, const float* __restrict__ b2n,
        int nnz) {
    const int bid = blockIdx.x;
    const int tid = threadIdx.x;

    if (bid < PF_BLOCKS) {
        // ---- prefetch ----
        const float4* __restrict__ a = reinterpret_cast<const float4*>(adj);
        const int total = PF_ROWS * NV4;
        float acc = 0.0f;
        for (int i = bid * 256 + tid; i < total; i += PF_BLOCKS * 256) {
            float4 v = __ldcg(&a[i]);
            acc += v.x + v.y + v.z + v.w;
        }
        if (acc == -1.2345678e-33f) g_sink = acc;   // keep loads alive
        return;
    }

    if (bid < PF_BLOCKS + SC_BLOCKS) {
        // ---- edge MLP + scatter ----
        __shared__ float sw1[PSI], sb1[PSI], sw2[PSI];
        __shared__ float sCp, sCn, sb2;
        __shared__ int sfast;
        if (tid < PSI) {
            sw1[tid] = w1e[tid];
            sb1[tid] = b1e[tid];
            sw2[tid] = w2e[tid];
        }
        if (tid == 0) sb2 = b2e[0];
        __syncthreads();
        if (tid == 0) {
            float cp = 0.0f, cn = 0.0f;
            int ok = 1;
#pragma unroll
            for (int j = 0; j < PSI; j++) {
                float w = sw1[j];
                float p = w * sw2[j];
                if (w > 0.0f) cp += p;
                else if (w < 0.0f) cn += p;
                if (sb1[j] != 0.0f) ok = 0;
            }
            sCp = cp; sCn = cn; sfast = ok;
        }
        __syncthreads();

        int i = (bid - PF_BLOCKS) * 256 + tid;
        if (i < nnz) {
            float v = values[i];
            float feat;
            if (sfast) {
                feat = fmaf(v, (v >= 0.0f) ? sCp : sCn, sb2);
            } else {
                float p0 = 0.0f, p1 = 0.0f, p2 = 0.0f, p3 = 0.0f;
#pragma unroll
                for (int j = 0; j < PSI; j += 4) {
                    p0 = fmaf(fmaxf(fmaf(v, sw1[j+0], sb1[j+0]), 0.0f), sw2[j+0], p0);
                    p1 = fmaf(fmaxf(fmaf(v, sw1[j+1], sb1[j+1]), 0.0f), sw2[j+1], p1);
                    p2 = fmaf(fmaxf(fmaf(v, sw1[j+2], sb1[j+2]), 0.0f), sw2[j+2], p2);
                    p3 = fmaf(fmaxf(fmaf(v, sw1[j+3], sb1[j+3]), 0.0f), sw2[j+3], p3);
                }
                feat = sb2 + (p0 + p1) + (p2 + p3);
            }
            atomicAdd(&g_agg[col[i]], feat);
        }
        __syncthreads();
        if (tid == 0) {
            __threadfence();
            atomicAdd(&g_sc_done, 1u);
        }
        return;
    }

    // ---- node MLP blocks ----
    {
        __shared__ float sw1[PSI], sb1[PSI], sw2[PSI], sb2;
        if (tid < PSI) {
            sw1[tid] = w1n[tid];
            sb1[tid] = b1n[tid];
            sw2[tid] = w2n[tid];
        }
        if (tid == 0) sb2 = b2n[0];
        __syncthreads();

        if (tid == 0) {
            while (atomicAdd(&g_sc_done, 0u) < SC_BLOCKS) __nanosleep(64);
        }
        __syncthreads();
        __threadfence();   // acquire g_agg

        const int nb = bid - (PF_BLOCKS + SC_BLOCKS);   // 0..NODE_BLOCKS-1
#pragma unroll
        for (int k = 0; k < 2; k++) {
            int n = nb * 512 + k * 256 + tid;           // 8192 nodes total
            float x = g_agg[n];
            g_agg[n] = 0.0f;                            // reset for next replay
            float p0 = 0.0f, p1 = 0.0f, p2 = 0.0f, p3 = 0.0f;
#pragma unroll
            for (int j = 0; j < PSI; j += 4) {
                p0 = fmaf(fmaxf(fmaf(x, sw1[j+0], sb1[j+0]), 0.0f), sw2[j+0], p0);
                p1 = fmaf(fmaxf(fmaf(x, sw1[j+1], sb1[j+1]), 0.0f), sw2[j+1], p1);
                p2 = fmaf(fmaxf(fmaf(x, sw1[j+2], sb1[j+2]), 0.0f), sw2[j+2], p2);
                p3 = fmaf(fmaxf(fmaf(x, sw1[j+3], sb1[j+3]), 0.0f), sw2[j+3], p3);
            }
            float acc = sb2 + (p0 + p1) + (p2 + p3);
            g_t[n] = acc * acc;
        }
    }
}

// ---------------------------------------------------------------------------
// K2: heterogeneous blocks.  PDL secondary (grid-sync on K1 completion).
//  [0, ROW_BLOCKS)   : grid-stride row score (R13's proven streaming body)
//  [ROW_BLOCKS, +GA) : spin on row_done, then gather out[e] = g_s[src[e]];
//                      last gather block resets all counters (replay-safe).
// Gather blocks exceed the 8-blocks/SM residency capacity, so they are
// dispatched only as row blocks retire -> internal spin cannot deadlock.
// ---------------------------------------------------------------------------
__global__ __launch_bounds__(256, 8) void k_back(
        const float* __restrict__ adj,
        const int* __restrict__ src_nodes,
        float* __restrict__ out, int E) {
    const int bid = blockIdx.x;
    const int tid = threadIdx.x;

    cudaGridDependencySynchronize();   // g_t ready (K1 complete)

    if (bid < ROW_BLOCKS) {
        __shared__ float warp_sum[8];
        const float4* __restrict__ tv = reinterpret_cast<const float4*>(g_t);

        for (int row = bid; row < N_NODES; row += ROW_BLOCKS) {
            const float4* __restrict__ a =
                reinterpret_cast<const float4*>(adj + (size_t)row * N_NODES);
            float acc = 0.0f;
#pragma unroll 4
            for (int i = tid; i < NV4; i += 256) {
                float4 av = __ldcs(&a[i]);
                float4 tw = __ldg(&tv[i]);
                acc = fmaf(av.x * av.x, tw.x, acc);
                acc = fmaf(av.y * av.y, tw.y, acc);
                acc = fmaf(av.z * av.z, tw.z, acc);
                acc = fmaf(av.w * av.w, tw.w, acc);
            }
#pragma unroll
            for (int off = 16; off > 0; off >>= 1)
                acc += __shfl_down_sync(0xffffffffu, acc, off);
            if ((tid & 31) == 0) warp_sum[tid >> 5] = acc;
            __syncthreads();
            if (tid < 8) {
                float v = warp_sum[tid];
#pragma unroll
                for (int off = 4; off > 0; off >>= 1)
                    v += __shfl_down_sync(0xffu, v, off);
                if (tid == 0) g_s[row] = v;
            }
            __syncthreads();
        }
        if (tid == 0) {
            __threadfence();
            atomicAdd(&g_row_done, 1u);
        }
        return;
    }

    // ---- gather blocks ----
    if (tid == 0) {
        while (atomicAdd(&g_row_done, 0u) < ROW_BLOCKS) __nanosleep(64);
    }
    __syncthreads();
    __threadfence();   // acquire g_s

    int e = (bid - ROW_BLOCKS) * 256 + tid;
    if (e < E) out[e] = g_s[src_nodes[e]];

    __syncthreads();
    if (tid == 0) {
        __threadfence();
        if (atomicAdd(&g_ga_done, 1u) == GA_BLOCKS - 1u) {
            // last gather block: reset pipeline counters for the next replay
            g_sc_done = 0;
            g_row_done = 0;
            g_ga_done = 0;
            __threadfence();
        }
    }
}

// ---------------------------------------------------------------------------
// launch helper: PDL launch (programmatic stream serialization)
// ---------------------------------------------------------------------------
template <typename... Args>
static inline void launch_pdl(void (*kern)(Args...), dim3 grid, dim3 block,
                              Args... args) {
    cudaLaunchAttribute attr[1];
    attr[0].id = cudaLaunchAttributeProgrammaticStreamSerialization;
    attr[0].val.programmaticStreamSerializationAllowed = 1;
    cudaLaunchConfig_t cfg{};
    cfg.gridDim = grid;
    cfg.blockDim = block;
    cfg.dynamicSmemBytes = 0;
    cfg.stream = 0;
    cfg.attrs = attr;
    cfg.numAttrs = 1;
    cudaLaunchKernelEx(&cfg, kern, args...);
}

// ---------------------------------------------------------------------------
// launch
// Inputs (metadata order): col, values, adj, src_nodes,
//                          w1e, b1e, w2e, b2e, w1n, b1n, w2n, b2n
// ---------------------------------------------------------------------------
extern "C" void kernel_launch(void* const* d_in, const int* in_sizes, int n_in,
                              void* d_out, int out_size) {
    const int*   col       = (const int*)d_in[0];
    const float* values    = (const float*)d_in[1];
    const float* adj       = (const float*)d_in[2];
    const int*   src_nodes = (const int*)d_in[3];
    const float* w1e = (const float*)d_in[4];
    const float* b1e = (const float*)d_in[5];
    const float* w2e = (const float*)d_in[6];
    const float* b2e = (const float*)d_in[7];
    const float* w1n = (const float*)d_in[8];
    const float* b1n = (const float*)d_in[9];
    const float* w2n = (const float*)d_in[10];
    const float* b2n = (const float*)d_in[11];
    float* out = (float*)d_out;

    const int nnz = in_sizes[0];   // 262144 = SC_BLOCKS * 256
    const int E   = in_sizes[3];   // 32768 = GA_BLOCKS * 256

    k_front<<<PF_BLOCKS + SC_BLOCKS + NODE_BLOCKS, 256>>>(
        adj, col, values, w1e, b1e, w2e, b2e, w1n, b1n, w2n, b2n, nnz);

    launch_pdl(k_back, dim3(ROW_BLOCKS + GA_BLOCKS), dim3(256),
               adj, src_nodes, out, E);
}

// round 16
// speedup vs baseline: 1.3895x; 1.3895x over previous
#include <cuda_runtime.h>

#define N_NODES 8192
#define NV4 (N_NODES / 4)       // 2048 float4 per row
#define PSI 64
#define GRID_RS 1184            // 148 SMs x 8 blocks, grid-stride over rows
#define PREFETCH_ROWS 1024      // 32 MB warmed into L2 during the scatter phase

// __device__ scratch (no allocations allowed).
// g_agg zero-init at load; node_mlp reads-then-zeros it each replay.
__device__ float g_agg[N_NODES];
__device__ float g_t[N_NODES];
__device__ float g_s[N_NODES];
__device__ float g_sink;        // prefetch DCE guard (never actually written)

// ---------------------------------------------------------------------------
// Kernel 0: L2 prefetch of the first PREFETCH_ROWS rows of adj.
// Triggers programmatic completion IMMEDIATELY so the (independent)
// edge_scatter launched behind it starts concurrently; this kernel then
// streams 32 MB into L2 during the otherwise DRAM-idle scatter phase.
// ---------------------------------------------------------------------------
__global__ __launch_bounds__(256) void k_prefetch(const float* __restrict__ adj) {
    cudaTriggerProgrammaticLaunchCompletion();   // release the next kernel now
    const float4* __restrict__ a = reinterpret_cast<const float4*>(adj);
    const int total = PREFETCH_ROWS * NV4;       // 2M float4
    float acc = 0.0f;
    for (int i = blockIdx.x * 256 + threadIdx.x; i < total; i += 512 * 256) {
        float4 v = __ldcg(&a[i]);                // L2-allocating load
        acc += v.x + v.y + v.z + v.w;
    }
    if (acc == -1.2345678e-33f) g_sink = acc;    // keep the loads alive
}

// ---------------------------------------------------------------------------
// Kernel 1: edge MLP + scatter-add by col.
// Algebraic fast path (zero hidden bias, verified on device):
//   f(v) = v*Cp + b2  (v >= 0),   f(v) = v*Cn + b2  (v < 0).
// Generic 64-term fallback keeps the kernel exact for arbitrary inputs.
// Launched with PDL but NO grid-sync: independent of the prefetch.
// ---------------------------------------------------------------------------
__global__ __launch_bounds__(256) void k_edge_scatter(
        const int* __restrict__ col,
        const float* __restrict__ values,
        const float* __restrict__ w1,
        const float* __restrict__ b1,
        const float* __restrict__ w2,
        const float* __restrict__ b2,
        int nnz) {
    __shared__ float sw1[PSI], sb1[PSI], sw2[PSI];
    __shared__ float sCp, sCn, sb2;
    __shared__ int sfast;
    if (threadIdx.x < PSI) {
        sw1[threadIdx.x] = w1[threadIdx.x];
        sb1[threadIdx.x] = b1[threadIdx.x];
        sw2[threadIdx.x] = w2[threadIdx.x];
    }
    if (threadIdx.x == 0) sb2 = b2[0];
    __syncthreads();
    if (threadIdx.x == 0) {
        float cp = 0.0f, cn = 0.0f;
        int ok = 1;
#pragma unroll
        for (int j = 0; j < PSI; j++) {
            float w = sw1[j];
            float p = w * sw2[j];
            if (w > 0.0f) cp += p;
            else if (w < 0.0f) cn += p;
            if (sb1[j] != 0.0f) ok = 0;
        }
        sCp = cp; sCn = cn; sfast = ok;
    }
    __syncthreads();

    int i = blockIdx.x * 256 + threadIdx.x;
    if (i >= nnz) return;
    float v = values[i];
    float feat;
    if (sfast) {
        feat = fmaf(v, (v >= 0.0f) ? sCp : sCn, sb2);
    } else {
        float p0 = 0.0f, p1 = 0.0f, p2 = 0.0f, p3 = 0.0f;
#pragma unroll
        for (int j = 0; j < PSI; j += 4) {
            p0 = fmaf(fmaxf(fmaf(v, sw1[j+0], sb1[j+0]), 0.0f), sw2[j+0], p0);
            p1 = fmaf(fmaxf(fmaf(v, sw1[j+1], sb1[j+1]), 0.0f), sw2[j+1], p1);
            p2 = fmaf(fmaxf(fmaf(v, sw1[j+2], sb1[j+2]), 0.0f), sw2[j+2], p2);
            p3 = fmaf(fmaxf(fmaf(v, sw1[j+3], sb1[j+3]), 0.0f), sw2[j+3], p3);
        }
        feat = sb2 + (p0 + p1) + (p2 + p3);
    }
    atomicAdd(&g_agg[col[i]], feat);
}

// ---------------------------------------------------------------------------
// Kernel 2: node MLP, store struct^2, re-zero g_agg for the next replay.
// PDL secondary (waits on edge_scatter).
// ---------------------------------------------------------------------------
__global__ __launch_bounds__(512) void k_node_mlp(
        const float* __restrict__ w1,
        const float* __restrict__ b1,
        const float* __restrict__ w2,
        const float* __restrict__ b2) {
    __shared__ float sw1[PSI], sb1[PSI], sw2[PSI], sb2;
    if (threadIdx.x < PSI) {
        sw1[threadIdx.x] = w1[threadIdx.x];
        sb1[threadIdx.x] = b1[threadIdx.x];
        sw2[threadIdx.x] = w2[threadIdx.x];
    }
    if (threadIdx.x == 0) sb2 = b2[0];
    __syncthreads();

    cudaGridDependencySynchronize();   // all g_agg atomics visible

    int i = blockIdx.x * 512 + threadIdx.x;
    if (i >= N_NODES) return;
    float x = g_agg[i];
    g_agg[i] = 0.0f;              // reset for next graph replay
    float p0 = 0.0f, p1 = 0.0f, p2 = 0.0f, p3 = 0.0f;
#pragma unroll
    for (int j = 0; j < PSI; j += 4) {
        p0 = fmaf(fmaxf(fmaf(x, sw1[j+0], sb1[j+0]), 0.0f), sw2[j+0], p0);
        p1 = fmaf(fmaxf(fmaf(x, sw1[j+1], sb1[j+1]), 0.0f), sw2[j+1], p1);
        p2 = fmaf(fmaxf(fmaf(x, sw1[j+2], sb1[j+2]), 0.0f), sw2[j+2], p2);
        p3 = fmaf(fmaxf(fmaf(x, sw1[j+3], sb1[j+3]), 0.0f), sw2[j+3], p3);
    }
    float acc = sb2 + (p0 + p1) + (p2 + p3);
    g_t[i] = acc * acc;
}

// ---------------------------------------------------------------------------
// Kernel 3: row score.  s[r] = sum_n adj[r,n]^2 * t[n]
// Measured-best body: grid-stride rows, grid 1184 (8 blocks/SM),
// unroll-4 streaming with __ldcs, smem block reduction.  Rows 0..1023 hit
// the L2 lines warmed by k_prefetch.  PDL secondary.
// ---------------------------------------------------------------------------
__global__ __launch_bounds__(256, 8) void k_row_score(const float* __restrict__ adj) {
    __shared__ float warp_sum[8];
    const float4* __restrict__ tv = reinterpret_cast<const float4*>(g_t);

    cudaGridDependencySynchronize();   // g_t ready

    for (int row = blockIdx.x; row < N_NODES; row += GRID_RS) {
        const float4* __restrict__ a =
            reinterpret_cast<const float4*>(adj + (size_t)row * N_NODES);
        float acc = 0.0f;
#pragma unroll 4
        for (int i = threadIdx.x; i < NV4; i += 256) {
            float4 av = __ldcs(&a[i]);
            float4 tw = __ldg(&tv[i]);
            acc = fmaf(av.x * av.x, tw.x, acc);
            acc = fmaf(av.y * av.y, tw.y, acc);
            acc = fmaf(av.z * av.z, tw.z, acc);
            acc = fmaf(av.w * av.w, tw.w, acc);
        }
#pragma unroll
        for (int off = 16; off > 0; off >>= 1)
            acc += __shfl_down_sync(0xffffffffu, acc, off);
        if ((threadIdx.x & 31) == 0) warp_sum[threadIdx.x >> 5] = acc;
        __syncthreads();
        if (threadIdx.x < 8) {
            float v = warp_sum[threadIdx.x];
#pragma unroll
            for (int off = 4; off > 0; off >>= 1)
                v += __shfl_down_sync(0xffu, v, off);
            if (threadIdx.x == 0) g_s[row] = v;
        }
        __syncthreads();   // warp_sum reuse next row
    }
}

// ---------------------------------------------------------------------------
// Kernel 4: gather per-edge output (g_s is L2-hot).  PDL secondary.
// ---------------------------------------------------------------------------
__global__ __launch_bounds__(256) void k_gather(const int* __restrict__ src_nodes,
                                                float* __restrict__ out, int E) {
    int e = blockIdx.x * 256 + threadIdx.x;
    cudaGridDependencySynchronize();   // g_s ready
    if (e < E) out[e] = g_s[src_nodes[e]];
}

// ---------------------------------------------------------------------------
// launch helper: PDL launch (programmatic stream serialization)
// ---------------------------------------------------------------------------
template <typename... Args>
static inline void launch_pdl(void (*kern)(Args...), dim3 grid, dim3 block,
                              Args... args) {
    cudaLaunchAttribute attr[1];
    attr[0].id = cudaLaunchAttributeProgrammaticStreamSerialization;
    attr[0].val.programmaticStreamSerializationAllowed = 1;
    cudaLaunchConfig_t cfg{};
    cfg.gridDim = grid;
    cfg.blockDim = block;
    cfg.dynamicSmemBytes = 0;
    cfg.stream = 0;
    cfg.attrs = attr;
    cfg.numAttrs = 1;
    cudaLaunchKernelEx(&cfg, kern, args...);
}

// ---------------------------------------------------------------------------
// launch
// Inputs (metadata order): col, values, adj, src_nodes,
//                          w1e, b1e, w2e, b2e, w1n, b1n, w2n, b2n
// ---------------------------------------------------------------------------
extern "C" void kernel_launch(void* const* d_in, const int* in_sizes, int n_in,
                              void* d_out, int out_size) {
    const int*   col       = (const int*)d_in[0];
    const float* values    = (const float*)d_in[1];
    const float* adj       = (const float*)d_in[2];
    const int*   src_nodes = (const int*)d_in[3];
    const float* w1e = (const float*)d_in[4];
    const float* b1e = (const float*)d_in[5];
    const float* w2e = (const float*)d_in[6];
    const float* b2e = (const float*)d_in[7];
    const float* w1n = (const float*)d_in[8];
    const float* b1n = (const float*)d_in[9];
    const float* w2n = (const float*)d_in[10];
    const float* b2n = (const float*)d_in[11];
    float* out = (float*)d_out;

    const int nnz = in_sizes[0];   // 262144
    const int E   = in_sizes[3];   // 32768

    // prefetch first (triggers immediately, so scatter overlaps it)
    k_prefetch<<<512, 256>>>(adj);

    // scatter: PDL, NO grid-sync inside (independent of prefetch)
    launch_pdl(k_edge_scatter, dim3((nnz + 255) / 256), dim3(256),
               col, values, w1e, b1e, w2e, b2e, nnz);

    // dependents: PDL with grid-sync
    launch_pdl(k_node_mlp, dim3((N_NODES + 511) / 512), dim3(512),
               w1n, b1n, w2n, b2n);
    launch_pdl(k_row_score, dim3(GRID_RS), dim3(256), adj);
    launch_pdl(k_gather, dim3((E + 255) / 256), dim3(256),
               src_nodes, out, E);
}